// round 5
// baseline (speedup 1.0000x reference)
#include <cuda_runtime.h>
#include <cuda_bf16.h>
#include <math.h>
#include <stdint.h>

// Problem constants
#define B_   1024
#define S_   128
#define D_   256
#define H_   2048
#define O_   10
#define V_   10

// Scratch (__device__ globals — no allocs allowed)
__device__ float g_h0[B_ * H_];
__device__ float g_h1[B_ * H_];
__device__ float g_T[V_ * H_];      // T[v,h] = (W_hx @ embed[v])[h] + b_hx[h]
__device__ float g_Wt[H_ * H_];     // tf32-rounded copy of W_hh

// round-to-nearest tf32 (result kept in fp32 bit pattern, low mantissa zeroed)
__device__ __forceinline__ float tf32r(float x) {
    uint32_t u;
    asm("cvt.rna.tf32.f32 %0, %1;" : "=r"(u) : "f"(x));
    return __uint_as_float(u);
}

// ---------------------------------------------------------------------------
// Kernel 1: T[v,h] = dot(W_hx[h,:], embed[v,:]) + b_hx[h]
// ---------------------------------------------------------------------------
__global__ void precompute_T_kernel(const float* __restrict__ embed,
                                    const float* __restrict__ W_hx,
                                    const float* __restrict__ b_hx) {
    int h = blockIdx.x * blockDim.x + threadIdx.x;
    int v = blockIdx.y;
    if (h >= H_) return;
    const float4* wr = reinterpret_cast<const float4*>(W_hx + (size_t)h * D_);
    const float4* er = reinterpret_cast<const float4*>(embed + (size_t)v * D_);
    float s = 0.f;
#pragma unroll 8
    for (int i = 0; i < D_ / 4; i++) {
        float4 w = wr[i];
        float4 e = er[i];
        s += w.x * e.x + w.y * e.y + w.z * e.z + w.w * e.w;
    }
    g_T[v * H_ + h] = s + b_hx[h];
}

// ---------------------------------------------------------------------------
// Kernel 1b: tf32-round W_hh into g_Wt
// ---------------------------------------------------------------------------
__global__ void round_W_kernel(const float* __restrict__ W) {
    int i = blockIdx.x * blockDim.x + threadIdx.x;
    g_Wt[i] = tf32r(W[i]);
}

// ---------------------------------------------------------------------------
// Kernel 2: h0 = tanh(T[x[:,0]]), rounded to tf32 for the first MMA
// ---------------------------------------------------------------------------
__global__ void init_h_kernel(const int* __restrict__ x) {
    int idx = blockIdx.x * blockDim.x + threadIdx.x;
    int b = idx >> 11;
    int h = idx & (H_ - 1);
    int tok = x[b * S_];
    g_h0[idx] = tf32r(tanhf(g_T[tok * H_ + h]));
}

// ---------------------------------------------------------------------------
// Kernel 3: recurrence step on tensor cores (tf32 mma.sync m16n8k8).
//   C = tf32round( tanh( A @ Wt^T + T[x[:,t]] + b_hh ) )
// Tile: BM=128 x BN=128 x BK=16, 256 threads, warp grid 2x4, warp tile 64x32.
//
// Smem layout (per 256-row buffer, 16 floats/row, no pad):
//   row r (A rows 0..127, B rows 128..255) stores k-values permuted:
//     p(k) = (k&3)*4 + (k>>2), quad-swizzled: quad' = quad ^ ((r>>1)&3)
//   => thread (g=lane>>2, c=lane&3) fragment = ONE float4 at [r][4*(c^swz)]
//      covering k = {c, c+4, c+8, c+12} (both k-steps of the 16-k tile).
//   Stores (STS.32) and fragment loads (LDS.128) are bank-conflict-free.
// ---------------------------------------------------------------------------
#define BM 128
#define BN 128
#define BK 16
#define NIT (H_ / BK)   // 128

__device__ __forceinline__ void mma_tf32(float* d,
                                         float a0, float a1, float a2, float a3,
                                         float b0, float b1) {
    uint32_t A0 = __float_as_uint(a0), A1 = __float_as_uint(a1);
    uint32_t A2 = __float_as_uint(a2), A3 = __float_as_uint(a3);
    uint32_t B0 = __float_as_uint(b0), B1 = __float_as_uint(b1);
    asm volatile(
        "mma.sync.aligned.m16n8k8.row.col.f32.tf32.tf32.f32 "
        "{%0,%1,%2,%3}, {%4,%5,%6,%7}, {%8,%9}, {%0,%1,%2,%3};\n"
        : "+f"(d[0]), "+f"(d[1]), "+f"(d[2]), "+f"(d[3])
        : "r"(A0), "r"(A1), "r"(A2), "r"(A3), "r"(B0), "r"(B1));
}

__global__ __launch_bounds__(256, 1)
void rnn_step_tc(int parity,
                 const float* __restrict__ bhh,
                 const int*   __restrict__ x,
                 int t) {
    const float* __restrict__ A = parity ? g_h1 : g_h0;
    float*       __restrict__ C = parity ? g_h0 : g_h1;
    const float* __restrict__ W = g_Wt;

    __shared__ float smem[2][256 * 16];

    const int tid = threadIdx.x;
    const int bm0 = blockIdx.y * BM;
    const int bn0 = blockIdx.x * BN;

    // ---- loader mapping: 4 threads per row, 1 float4 (quad) each ----
    const int lq = tid & 3;          // which k-quad (global k offset lq*4)
    const int lr = tid >> 2;         // 0..63
    const float* gA0 = A + (size_t)(bm0 + lr)      * H_ + lq * 4;
    const float* gA1 = A + (size_t)(bm0 + lr + 64) * H_ + lq * 4;
    const float* gW0 = W + (size_t)(bn0 + lr)      * H_ + lq * 4;
    const float* gW1 = W + (size_t)(bn0 + lr + 64) * H_ + lq * 4;
    const int RA0 = lr, RA1 = lr + 64, RB0 = 128 + lr, RB1 = 128 + lr + 64;

    // ---- mma fragment mapping ----
    const int warp = tid >> 5, lane = tid & 31;
    const int wm = warp >> 2;        // 0..1
    const int wn = warp & 3;         // 0..3
    const int g  = lane >> 2;        // 0..7
    const int cc = lane & 3;         // 0..3

    int offAlo[4], offB[4];
#pragma unroll
    for (int f = 0; f < 4; f++) {
        int rl = wm * 64 + f * 16 + g;
        offAlo[f] = rl * 16 + 4 * (cc ^ ((rl >> 1) & 3));
    }
#pragma unroll
    for (int n = 0; n < 4; n++) {
        int rb = 128 + wn * 32 + n * 8 + g;
        offB[n] = rb * 16 + 4 * (cc ^ ((rb >> 1) & 3));
    }

    float acc[4][4][4];
#pragma unroll
    for (int f = 0; f < 4; f++)
#pragma unroll
        for (int n = 0; n < 4; n++)
#pragma unroll
            for (int k = 0; k < 4; k++) acc[f][n][k] = 0.f;

    // STS of one loaded quad: element j (global k = lq*4+j? no: k = 4*lq + j,
    // permuted position p = j*4 + lq) -> smem[R*16 + 4*(j ^ ((R>>1)&3)) + lq]
    float4 pf0, pf1, pf2, pf3;

#define STS_ROW(SB, R, V)                                  \
    do {                                                   \
        int _x = ((R) >> 1) & 3;                           \
        int _b = (R) * 16 + lq;                            \
        (SB)[_b + 4 * (0 ^ _x)] = (V).x;                   \
        (SB)[_b + 4 * (1 ^ _x)] = (V).y;                   \
        (SB)[_b + 4 * (2 ^ _x)] = (V).z;                   \
        (SB)[_b + 4 * (3 ^ _x)] = (V).w;                   \
    } while (0)

    // ---- prologue: tile0 -> smem[0]; prefetch tile1 -> regs ----
    pf0 = *(const float4*)(gA0);
    pf1 = *(const float4*)(gA1);
    pf2 = *(const float4*)(gW0);
    pf3 = *(const float4*)(gW1);
    {
        float* sb = smem[0];
        STS_ROW(sb, RA0, pf0); STS_ROW(sb, RA1, pf1);
        STS_ROW(sb, RB0, pf2); STS_ROW(sb, RB1, pf3);
    }
    pf0 = *(const float4*)(gA0 + BK);
    pf1 = *(const float4*)(gA1 + BK);
    pf2 = *(const float4*)(gW0 + BK);
    pf3 = *(const float4*)(gW1 + BK);
    __syncthreads();

    int buf = 0;
#pragma unroll 1
    for (int it = 0; it < NIT; ++it) {
        // stage prefetched tile (it+1) into the other buffer
        if (it + 1 < NIT) {
            float* sb1 = smem[buf ^ 1];
            STS_ROW(sb1, RA0, pf0); STS_ROW(sb1, RA1, pf1);
            STS_ROW(sb1, RB0, pf2); STS_ROW(sb1, RB1, pf3);
        }
        // issue loads for tile (it+2)
        if (it + 2 < NIT) {
            int k0 = (it + 2) * BK;
            pf0 = *(const float4*)(gA0 + k0);
            pf1 = *(const float4*)(gA1 + k0);
            pf2 = *(const float4*)(gW0 + k0);
            pf3 = *(const float4*)(gW1 + k0);
        }

        // compute on current buffer
        const float* sb = smem[buf];
        float4 alo[4], ahi[4], bq[4];
#pragma unroll
        for (int f = 0; f < 4; f++) {
            alo[f] = *(const float4*)(sb + offAlo[f]);
            ahi[f] = *(const float4*)(sb + offAlo[f] + 128);   // row+8, same swizzle
        }
#pragma unroll
        for (int n = 0; n < 4; n++) bq[n] = *(const float4*)(sb + offB[n]);

        // k-step 0: k = {cc, cc+4}
#pragma unroll
        for (int f = 0; f < 4; f++)
#pragma unroll
            for (int n = 0; n < 4; n++)
                mma_tf32(acc[f][n], alo[f].x, ahi[f].x, alo[f].y, ahi[f].y,
                         bq[n].x, bq[n].y);
        // k-step 1: k = {cc+8, cc+12}
#pragma unroll
        for (int f = 0; f < 4; f++)
#pragma unroll
            for (int n = 0; n < 4; n++)
                mma_tf32(acc[f][n], alo[f].z, ahi[f].z, alo[f].w, ahi[f].w,
                         bq[n].z, bq[n].w);

        __syncthreads();
        buf ^= 1;
    }

    // ---- fused epilogue: + T[x[b,t]] + b_hh, tanh, tf32-round, store ----
#pragma unroll
    for (int f = 0; f < 4; f++) {
        int rlo = bm0 + wm * 64 + f * 16 + g;
        int rhi = rlo + 8;
        int tlo = x[rlo * S_ + t];
        int thi = x[rhi * S_ + t];
        const float* Tlo = g_T + tlo * H_;
        const float* Thi = g_T + thi * H_;
#pragma unroll
        for (int n = 0; n < 4; n++) {
            int col = bn0 + wn * 32 + n * 8 + cc * 2;
            float bb0 = bhh[col], bb1 = bhh[col + 1];
            float2 o;
            o.x = tf32r(tanhf(acc[f][n][0] + Tlo[col]     + bb0));
            o.y = tf32r(tanhf(acc[f][n][1] + Tlo[col + 1] + bb1));
            *(float2*)(C + (size_t)rlo * H_ + col) = o;
            o.x = tf32r(tanhf(acc[f][n][2] + Thi[col]     + bb0));
            o.y = tf32r(tanhf(acc[f][n][3] + Thi[col + 1] + bb1));
            *(float2*)(C + (size_t)rhi * H_ + col) = o;
        }
    }
#undef STS_ROW
}

// ---------------------------------------------------------------------------
// Kernel 4: o = hT @ W_oh^T + b_oh ; softmax over O=10.
// ---------------------------------------------------------------------------
__global__ __launch_bounds__(256)
void output_softmax_kernel(const float* __restrict__ W_oh,
                           const float* __restrict__ b_oh,
                           float* __restrict__ out) {
    const int b = blockIdx.x;
    const int tid = threadIdx.x;
    const float* hrow = g_h1 + (size_t)b * H_;

    float acc[O_];
#pragma unroll
    for (int j = 0; j < O_; j++) acc[j] = 0.f;

    for (int k = tid; k < H_; k += 256) {
        float hv = hrow[k];
#pragma unroll
        for (int j = 0; j < O_; j++) acc[j] += hv * W_oh[j * H_ + k];
    }
#pragma unroll
    for (int off = 16; off > 0; off >>= 1)
#pragma unroll
        for (int j = 0; j < O_; j++)
            acc[j] += __shfl_down_sync(0xffffffffu, acc[j], off);

    __shared__ float part[8][O_];
    if ((tid & 31) == 0) {
#pragma unroll
        for (int j = 0; j < O_; j++) part[tid >> 5][j] = acc[j];
    }
    __syncthreads();

    if (tid == 0) {
        float o[O_];
#pragma unroll
        for (int j = 0; j < O_; j++) {
            float s = b_oh[j];
#pragma unroll
            for (int w = 0; w < 8; w++) s += part[w][j];
            o[j] = s;
        }
        float m = o[0];
#pragma unroll
        for (int j = 1; j < O_; j++) m = fmaxf(m, o[j]);
        float s = 0.f;
#pragma unroll
        for (int j = 0; j < O_; j++) { o[j] = expf(o[j] - m); s += o[j]; }
        float inv = 1.f / s;
#pragma unroll
        for (int j = 0; j < O_; j++) out[b * O_ + j] = o[j] * inv;
    }
}

// ---------------------------------------------------------------------------
// Launch (graph-capturable, no allocs/syncs).
// Inputs: x, embed, W_hx, b_hx, W_hh, b_hh, W_oh, b_oh
// ---------------------------------------------------------------------------
extern "C" void kernel_launch(void* const* d_in, const int* in_sizes, int n_in,
                              void* d_out, int out_size) {
    const int*   x     = (const int*)  d_in[0];
    const float* embed = (const float*)d_in[1];
    const float* W_hx  = (const float*)d_in[2];
    const float* b_hx  = (const float*)d_in[3];
    const float* W_hh  = (const float*)d_in[4];
    const float* b_hh  = (const float*)d_in[5];
    const float* W_oh  = (const float*)d_in[6];
    const float* b_oh  = (const float*)d_in[7];
    float* out = (float*)d_out;

    precompute_T_kernel<<<dim3(H_ / 256, V_), 256>>>(embed, W_hx, b_hx);
    round_W_kernel<<<(H_ * H_) / 256, 256>>>(W_hh);
    init_h_kernel<<<(B_ * H_) / 256, 256>>>(x);

    dim3 grid(H_ / BN, B_ / BM);   // (16, 8) = 128 CTAs
    for (int t = 1; t < S_; t++) {
        int parity = (t - 1) & 1;
        rnn_step_tc<<<grid, 256>>>(parity, b_hh, x, t);
    }

    output_softmax_kernel<<<B_, 256>>>(W_oh, b_oh, out);
}

// round 7
// speedup vs baseline: 2.7070x; 2.7070x over previous
#include <cuda_runtime.h>
#include <cuda_fp16.h>
#include <math.h>
#include <stdint.h>

// Problem constants
#define B_   1024
#define S_   128
#define D_   256
#define H_   2048
#define O_   10
#define V_   10

// Step-kernel tiling
#define BM   128
#define BN   128
#define KT   64            // fp16 per K-tile => 128 bytes/row (SW128 atom)
#define NKT  (H_ / KT)     // 32
#define NB   3             // triple-buffered smem
#define TILE_BYTES 16384   // 128 rows x 128B

// Scratch (__device__ globals)
__device__ __half g_h0[B_ * H_];
__device__ __half g_h1[B_ * H_];
__device__ float  g_T[V_ * H_];     // T[v,h] = (W_hx @ embed[v])[h] + b_hx[h]
__device__ __half g_Wh[H_ * H_];    // fp16 W_hh, row-major [h][k]

// ---------------------------------------------------------------------------
// helpers
// ---------------------------------------------------------------------------
__device__ __forceinline__ uint32_t smem_u32(const void* p) {
    uint32_t a;
    asm("{ .reg .u64 t; cvta.to.shared.u64 t, %1; cvt.u32.u64 %0, t; }" : "=r"(a) : "l"(p));
    return a;
}
#define SWZ128(o) ((o) ^ (((o) >> 3) & 0x70))

#define CP_ASYNC16(dst, src) \
    asm volatile("cp.async.cg.shared.global [%0], [%1], 16;\n" :: "r"(dst), "l"(src))
#define CP_COMMIT() asm volatile("cp.async.commit_group;\n" ::: "memory")
#define CP_WAIT(n)  asm volatile("cp.async.wait_group %0;\n" :: "n"(n) : "memory")

#define LDSM4(R, A)                                                        \
    asm volatile("ldmatrix.sync.aligned.m8n8.x4.shared.b16 "               \
                 "{%0,%1,%2,%3}, [%4];"                                    \
                 : "=r"((R)[0]), "=r"((R)[1]), "=r"((R)[2]), "=r"((R)[3])  \
                 : "r"(A))

__device__ __forceinline__ void mma16816(float* d, const uint32_t* a,
                                         uint32_t b0, uint32_t b1) {
    asm volatile(
        "mma.sync.aligned.m16n8k16.row.col.f32.f16.f16.f32 "
        "{%0,%1,%2,%3}, {%4,%5,%6,%7}, {%8,%9}, {%0,%1,%2,%3};\n"
        : "+f"(d[0]), "+f"(d[1]), "+f"(d[2]), "+f"(d[3])
        : "r"(a[0]), "r"(a[1]), "r"(a[2]), "r"(a[3]), "r"(b0), "r"(b1));
}

// ---------------------------------------------------------------------------
// Kernel 1: T[v,h] = dot(W_hx[h,:], embed[v,:]) + b_hx[h]
// ---------------------------------------------------------------------------
__global__ void precompute_T_kernel(const float* __restrict__ embed,
                                    const float* __restrict__ W_hx,
                                    const float* __restrict__ b_hx) {
    int h = blockIdx.x * blockDim.x + threadIdx.x;
    int v = blockIdx.y;
    if (h >= H_) return;
    const float4* wr = reinterpret_cast<const float4*>(W_hx + (size_t)h * D_);
    const float4* er = reinterpret_cast<const float4*>(embed + (size_t)v * D_);
    float s = 0.f;
#pragma unroll 8
    for (int i = 0; i < D_ / 4; i++) {
        float4 w = wr[i];
        float4 e = er[i];
        s += w.x * e.x + w.y * e.y + w.z * e.z + w.w * e.w;
    }
    g_T[v * H_ + h] = s + b_hx[h];
}

// Kernel 1b: fp16 copy of W_hh
__global__ void cvt_W_kernel(const float* __restrict__ W) {
    int i = blockIdx.x * blockDim.x + threadIdx.x;
    g_Wh[i] = __float2half(W[i]);
}

// Kernel 2: h0 = tanh(T[x[:,0]]) in fp16
__global__ void init_h_kernel(const int* __restrict__ x) {
    int idx = blockIdx.x * blockDim.x + threadIdx.x;
    int b = idx >> 11;
    int h = idx & (H_ - 1);
    int tok = x[b * S_];
    g_h0[idx] = __float2half(tanhf(g_T[tok * H_ + h]));
}

// ---------------------------------------------------------------------------
// Kernel 3: recurrence step. C = fp16(tanh(A @ Wh^T + T[x[:,t]] + b_hh))
// 128x128x2048 per CTA, grid (16,8) = 128 CTAs. 256 threads, 8 warps (2x4),
// warp tile 64x32. cp.async triple-buffered 64-K fp16 tiles (SW128 swizzle),
// ldmatrix.x4 fragments, mma.sync.m16n8k16 fp16->fp32.
// ---------------------------------------------------------------------------
__global__ __launch_bounds__(256, 1)
void rnn_step_hmma(int parity,
                   const float* __restrict__ bhh,
                   const int*   __restrict__ x,
                   int t) {
    const __half* __restrict__ Ag = parity ? g_h1 : g_h0;
    __half*       __restrict__ Cg = parity ? g_h0 : g_h1;

    extern __shared__ char dsm[];
    const uint32_t sraw = smem_u32(dsm);
    const uint32_t smA  = (sraw + 1023) & ~1023u;
    const uint32_t smB  = smA + NB * TILE_BYTES;

    const int tid  = threadIdx.x;
    const int warp = tid >> 5;
    const int lane = tid & 31;
    const int bm0  = blockIdx.y * BM;
    const int bn0  = blockIdx.x * BN;
    const int wm   = warp >> 2;      // 0..1  (M half)
    const int wn   = warp & 3;       // 0..3  (N quarter)

    // ---- loader mapping: per thread 8 x cp.async(16B): 4 A rows + 4 B rows ----
    const int ch8 = tid & 7;         // 16B chunk within 128B row
    const int r0  = tid >> 3;        // 0..31
    const char* gA[4];
    const char* gB[4];
    uint32_t offR[4];
#pragma unroll
    for (int j = 0; j < 4; j++) {
        int row = r0 + 32 * j;
        gA[j] = (const char*)(Ag   + (size_t)(bm0 + row) * H_) + ch8 * 16;
        gB[j] = (const char*)(g_Wh + (size_t)(bn0 + row) * H_) + ch8 * 16;
        offR[j] = SWZ128((uint32_t)(row * 128 + ch8 * 16));
    }

#define LOAD_TILE(TT, BUF)                                            \
    do {                                                              \
        size_t _kb = (size_t)(TT) * 128;                              \
        uint32_t _da = smA + (BUF) * TILE_BYTES;                      \
        uint32_t _db = smB + (BUF) * TILE_BYTES;                      \
        CP_ASYNC16(_da + offR[0], gA[0] + _kb);                       \
        CP_ASYNC16(_da + offR[1], gA[1] + _kb);                       \
        CP_ASYNC16(_da + offR[2], gA[2] + _kb);                       \
        CP_ASYNC16(_da + offR[3], gA[3] + _kb);                       \
        CP_ASYNC16(_db + offR[0], gB[0] + _kb);                       \
        CP_ASYNC16(_db + offR[1], gB[1] + _kb);                       \
        CP_ASYNC16(_db + offR[2], gB[2] + _kb);                       \
        CP_ASYNC16(_db + offR[3], gB[3] + _kb);                       \
        CP_COMMIT();                                                  \
    } while (0)

    // ---- ldmatrix lane-address precompute ----
    // A frag f (m16): rows = wm*64 + f*16 + (lane&7) + ((lane>>3)&1)*8
    //                 k-chunk parity pA = lane>>4 (0: k0-7, 1: k8-15)
    uint32_t rA128[4], rA7[4];
    const uint32_t pA = lane >> 4;
#pragma unroll
    for (int f = 0; f < 4; f++) {
        uint32_t r = wm * 64 + f * 16 + (lane & 7) + ((lane >> 3) & 1) * 8;
        rA128[f] = r * 128;
        rA7[f]   = r & 7;
    }
    // B frag q (n16 group): rows(n) = wn*32 + q*16 + (lane&7) + ((lane>>4)&1)*8
    //                       k-chunk parity pB = (lane>>3)&1
    uint32_t rB128[2], rB7[2];
    const uint32_t pB = (lane >> 3) & 1;
#pragma unroll
    for (int q = 0; q < 2; q++) {
        uint32_t r = wn * 32 + q * 16 + (lane & 7) + ((lane >> 4) & 1) * 8;
        rB128[q] = r * 128;
        rB7[q]   = r & 7;
    }

    float acc[4][4][4];
#pragma unroll
    for (int f = 0; f < 4; f++)
#pragma unroll
        for (int n = 0; n < 4; n++)
#pragma unroll
            for (int k = 0; k < 4; k++) acc[f][n][k] = 0.f;

    // ---- prologue: tiles 0,1 in flight ----
    LOAD_TILE(0, 0);
    LOAD_TILE(1, 1);

    int buf = 0;
#pragma unroll 1
    for (int it = 0; it < NKT; ++it) {
        if (it == NKT - 1) { CP_WAIT(0); } else { CP_WAIT(1); }
        __syncthreads();
        if (it + 2 < NKT) LOAD_TILE(it + 2, (it + 2) % NB);

        const uint32_t sa = smA + buf * TILE_BYTES;
        const uint32_t sb = smB + buf * TILE_BYTES;

#pragma unroll
        for (int s = 0; s < 4; s++) {           // k16 steps within 64-K tile
            uint32_t afr[4][4], bfr[2][4];
#pragma unroll
            for (int f = 0; f < 4; f++) {
                uint32_t addr = sa + rA128[f] + (((2u * s + pA) ^ rA7[f]) << 4);
                LDSM4(afr[f], addr);
            }
#pragma unroll
            for (int q = 0; q < 2; q++) {
                uint32_t addr = sb + rB128[q] + (((2u * s + pB) ^ rB7[q]) << 4);
                LDSM4(bfr[q], addr);
            }
#pragma unroll
            for (int f = 0; f < 4; f++)
#pragma unroll
                for (int n = 0; n < 4; n++)
                    mma16816(acc[f][n], afr[f],
                             bfr[n >> 1][(n & 1) * 2], bfr[n >> 1][(n & 1) * 2 + 1]);
        }

        buf++; if (buf == NB) buf = 0;
    }

    // ---- fused epilogue: + T[x[b,t]] + b_hh, tanh, fp16 store ----
#pragma unroll
    for (int f = 0; f < 4; f++) {
        int rlo = bm0 + wm * 64 + f * 16 + (lane >> 2);
        int rhi = rlo + 8;
        int tlo = x[rlo * S_ + t];
        int thi = x[rhi * S_ + t];
        const float* Tlo = g_T + tlo * H_;
        const float* Thi = g_T + thi * H_;
#pragma unroll
        for (int n = 0; n < 4; n++) {
            int col = bn0 + wn * 32 + n * 8 + (lane & 3) * 2;
            float bb0 = bhh[col], bb1 = bhh[col + 1];
            float v0 = tanhf(acc[f][n][0] + Tlo[col]     + bb0);
            float v1 = tanhf(acc[f][n][1] + Tlo[col + 1] + bb1);
            *(__half2*)(Cg + (size_t)rlo * H_ + col) = __floats2half2_rn(v0, v1);
            v0 = tanhf(acc[f][n][2] + Thi[col]     + bb0);
            v1 = tanhf(acc[f][n][3] + Thi[col + 1] + bb1);
            *(__half2*)(Cg + (size_t)rhi * H_ + col) = __floats2half2_rn(v0, v1);
        }
    }
#undef LOAD_TILE
}

// ---------------------------------------------------------------------------
// Kernel 4: o = hT @ W_oh^T + b_oh ; softmax over O=10 (h fp16)
// ---------------------------------------------------------------------------
__global__ __launch_bounds__(256)
void output_softmax_kernel(const float* __restrict__ W_oh,
                           const float* __restrict__ b_oh,
                           float* __restrict__ out) {
    const int b = blockIdx.x;
    const int tid = threadIdx.x;
    const __half* hrow = g_h1 + (size_t)b * H_;

    float acc[O_];
#pragma unroll
    for (int j = 0; j < O_; j++) acc[j] = 0.f;

    for (int k = tid; k < H_; k += 256) {
        float hv = __half2float(hrow[k]);
#pragma unroll
        for (int j = 0; j < O_; j++) acc[j] += hv * W_oh[j * H_ + k];
    }
#pragma unroll
    for (int off = 16; off > 0; off >>= 1)
#pragma unroll
        for (int j = 0; j < O_; j++)
            acc[j] += __shfl_down_sync(0xffffffffu, acc[j], off);

    __shared__ float part[8][O_];
    if ((tid & 31) == 0) {
#pragma unroll
        for (int j = 0; j < O_; j++) part[tid >> 5][j] = acc[j];
    }
    __syncthreads();

    if (tid == 0) {
        float o[O_];
#pragma unroll
        for (int j = 0; j < O_; j++) {
            float s = b_oh[j];
#pragma unroll
            for (int w = 0; w < 8; w++) s += part[w][j];
            o[j] = s;
        }
        float m = o[0];
#pragma unroll
        for (int j = 1; j < O_; j++) m = fmaxf(m, o[j]);
        float s = 0.f;
#pragma unroll
        for (int j = 0; j < O_; j++) { o[j] = expf(o[j] - m); s += o[j]; }
        float inv = 1.f / s;
#pragma unroll
        for (int j = 0; j < O_; j++) out[b * O_ + j] = o[j] * inv;
    }
}

// ---------------------------------------------------------------------------
// Launch (graph-capturable; no allocs/syncs).
// Inputs: x, embed, W_hx, b_hx, W_hh, b_hh, W_oh, b_oh
// ---------------------------------------------------------------------------
#define STEP_SMEM (1024 + 2 * NB * TILE_BYTES)

extern "C" void kernel_launch(void* const* d_in, const int* in_sizes, int n_in,
                              void* d_out, int out_size) {
    const int*   x     = (const int*)  d_in[0];
    const float* embed = (const float*)d_in[1];
    const float* W_hx  = (const float*)d_in[2];
    const float* b_hx  = (const float*)d_in[3];
    const float* W_hh  = (const float*)d_in[4];
    const float* b_hh  = (const float*)d_in[5];
    const float* W_oh  = (const float*)d_in[6];
    const float* b_oh  = (const float*)d_in[7];
    float* out = (float*)d_out;

    static int attr_set = 0;
    if (!attr_set) {
        cudaFuncSetAttribute(rnn_step_hmma,
                             cudaFuncAttributeMaxDynamicSharedMemorySize, STEP_SMEM);
        attr_set = 1;
    }

    precompute_T_kernel<<<dim3(H_ / 256, V_), 256>>>(embed, W_hx, b_hx);
    cvt_W_kernel<<<(H_ * H_) / 256, 256>>>(W_hh);
    init_h_kernel<<<(B_ * H_) / 256, 256>>>(x);

    dim3 grid(H_ / BN, B_ / BM);   // (16, 8) = 128 CTAs
    for (int t = 1; t < S_; t++) {
        int parity = (t - 1) & 1;
        rnn_step_hmma<<<grid, 256, STEP_SMEM>>>(parity, b_hh, x, t);
    }

    output_softmax_kernel<<<B_, 256>>>(W_oh, b_oh, out);
}

// round 8
// speedup vs baseline: 2.7600x; 1.0196x over previous
#include <cuda_runtime.h>
#include <cuda_fp16.h>
#include <math.h>
#include <stdint.h>

// Problem constants
#define B_   1024
#define S_   128
#define D_   256
#define H_   2048
#define O_   10
#define V_   10

// Step tiling
#define BM   128
#define BN   128
#define KT   64            // fp16 per K-tile => 128B/row (SW128 atom)
#define NKT  (H_ / KT)     // 32
#define NB   4             // 4-stage cp.async pipeline
#define TILE_BYTES 16384   // 128 rows x 128B

// Scratch
__device__ __half g_h0[B_ * H_];
__device__ __half g_h1[B_ * H_];
__device__ float  g_T [V_ * H_];    // W_hx @ embed[v] + b_hx   (for h0)
__device__ float  g_T2[V_ * H_];    // g_T + b_hh               (for steps)
__device__ __half g_Wh[H_ * H_];    // fp16 W_hh, row-major [h][k]
__device__ unsigned g_bar;          // grid barrier (cumulative)

// ---------------------------------------------------------------------------
// helpers
// ---------------------------------------------------------------------------
__device__ __forceinline__ uint32_t smem_u32(const void* p) {
    uint32_t a;
    asm("{ .reg .u64 t; cvta.to.shared.u64 t, %1; cvt.u32.u64 %0, t; }" : "=r"(a) : "l"(p));
    return a;
}
#define SWZ128(o) ((o) ^ (((o) >> 3) & 0x70))

#define CP_ASYNC16(dst, src) \
    asm volatile("cp.async.cg.shared.global [%0], [%1], 16;\n" :: "r"(dst), "l"(src))
#define CP_COMMIT() asm volatile("cp.async.commit_group;\n" ::: "memory")
#define CP_WAIT(n)  asm volatile("cp.async.wait_group %0;\n" :: "n"(n) : "memory")

#define LDSM4(R, A)                                                        \
    asm volatile("ldmatrix.sync.aligned.m8n8.x4.shared.b16 "               \
                 "{%0,%1,%2,%3}, [%4];"                                    \
                 : "=r"((R)[0]), "=r"((R)[1]), "=r"((R)[2]), "=r"((R)[3])  \
                 : "r"(A))

__device__ __forceinline__ void mma16816(float* d, const uint32_t* a,
                                         uint32_t b0, uint32_t b1) {
    asm volatile(
        "mma.sync.aligned.m16n8k16.row.col.f32.f16.f16.f32 "
        "{%0,%1,%2,%3}, {%4,%5,%6,%7}, {%8,%9}, {%0,%1,%2,%3};\n"
        : "+f"(d[0]), "+f"(d[1]), "+f"(d[2]), "+f"(d[3])
        : "r"(a[0]), "r"(a[1]), "r"(a[2]), "r"(a[3]), "r"(b0), "r"(b1));
}

// tanh(x) = 1 - 2/(e^{2x}+1) via MUFU ex2 + rcp; rel err ~1e-6, saturates cleanly.
__device__ __forceinline__ float fast_tanh(float x) {
    float e;
    asm("ex2.approx.f32 %0, %1;" : "=f"(e) : "f"(x * 2.8853900817779268f));
    float r;
    asm("rcp.approx.f32 %0, %1;" : "=f"(r) : "f"(e + 1.0f));
    return fmaf(-2.0f, r, 1.0f);
}

// ---------------------------------------------------------------------------
// Setup kernels
// ---------------------------------------------------------------------------
__global__ void precompute_T_kernel(const float* __restrict__ embed,
                                    const float* __restrict__ W_hx,
                                    const float* __restrict__ b_hx) {
    int h = blockIdx.x * blockDim.x + threadIdx.x;
    int v = blockIdx.y;
    if (h >= H_) return;
    const float4* wr = reinterpret_cast<const float4*>(W_hx + (size_t)h * D_);
    const float4* er = reinterpret_cast<const float4*>(embed + (size_t)v * D_);
    float s = 0.f;
#pragma unroll 8
    for (int i = 0; i < D_ / 4; i++) {
        float4 w = wr[i];
        float4 e = er[i];
        s += w.x * e.x + w.y * e.y + w.z * e.z + w.w * e.w;
    }
    g_T[v * H_ + h] = s + b_hx[h];
}

__global__ void make_T2_kernel(const float* __restrict__ b_hh) {
    int i = blockIdx.x * blockDim.x + threadIdx.x;   // v*H + h
    g_T2[i] = g_T[i] + b_hh[i & (H_ - 1)];
}

__global__ void cvt_W_kernel(const float* __restrict__ W) {
    int i = blockIdx.x * blockDim.x + threadIdx.x;
    g_Wh[i] = __float2half(W[i]);
}

// h0 = tanh(T[x[:,0]]) in fp16; also resets grid barrier for this launch
__global__ void init_h_kernel(const int* __restrict__ x) {
    int idx = blockIdx.x * blockDim.x + threadIdx.x;
    if (idx == 0) g_bar = 0u;
    int b = idx >> 11;
    int h = idx & (H_ - 1);
    int tok = x[b * S_];
    g_h0[idx] = __float2half(fast_tanh(g_T[tok * H_ + h]));
}

// ---------------------------------------------------------------------------
// Persistent recurrence kernel: all 127 steps in one launch.
// Grid (16,8)=128 CTAs (one wave, all resident), 256 threads, warp tile 64x32.
// Per step: 128x128x2048 fp16 HMMA GEMM, fused epilogue, grid barrier.
// ---------------------------------------------------------------------------
__global__ __launch_bounds__(256, 1)
void rnn_persist(const int* __restrict__ x) {
    extern __shared__ char dsm[];
    const uint32_t sraw = smem_u32(dsm);
    const uint32_t smA  = (sraw + 1023) & ~1023u;
    const uint32_t smB  = smA + NB * TILE_BYTES;

    const int tid  = threadIdx.x;
    const int warp = tid >> 5;
    const int lane = tid & 31;
    const int bm0  = blockIdx.y * BM;
    const int bn0  = blockIdx.x * BN;
    const int wm   = warp >> 2;
    const int wn   = warp & 3;

    // ---- loader mapping: 8 x cp.async(16B) per thread: 4 A rows + 4 B rows ----
    const int ch8 = tid & 7;
    const int r0  = tid >> 3;
    size_t aoff[4];                 // byte offset of A row chunk (excl. base)
    const char* gB[4];
    uint32_t offR[4];
#pragma unroll
    for (int j = 0; j < 4; j++) {
        int row = r0 + 32 * j;
        aoff[j] = (size_t)(bm0 + row) * H_ * 2 + ch8 * 16;
        gB[j]   = (const char*)(g_Wh + (size_t)(bn0 + row) * H_) + ch8 * 16;
        offR[j] = SWZ128((uint32_t)(row * 128 + ch8 * 16));
    }

#define LOAD_TILE(ABASE, TT, BUF)                                     \
    do {                                                              \
        size_t _kb = (size_t)(TT) * 128;                              \
        uint32_t _da = smA + (BUF) * TILE_BYTES;                      \
        uint32_t _db = smB + (BUF) * TILE_BYTES;                      \
        CP_ASYNC16(_da + offR[0], (ABASE) + aoff[0] + _kb);           \
        CP_ASYNC16(_da + offR[1], (ABASE) + aoff[1] + _kb);           \
        CP_ASYNC16(_da + offR[2], (ABASE) + aoff[2] + _kb);           \
        CP_ASYNC16(_da + offR[3], (ABASE) + aoff[3] + _kb);           \
        CP_ASYNC16(_db + offR[0], gB[0] + _kb);                       \
        CP_ASYNC16(_db + offR[1], gB[1] + _kb);                       \
        CP_ASYNC16(_db + offR[2], gB[2] + _kb);                       \
        CP_ASYNC16(_db + offR[3], gB[3] + _kb);                       \
        CP_COMMIT();                                                  \
    } while (0)

    // ---- ldmatrix lane addresses ----
    uint32_t rA128[4], rA7[4];
    const uint32_t pA = lane >> 4;
#pragma unroll
    for (int f = 0; f < 4; f++) {
        uint32_t r = wm * 64 + f * 16 + (lane & 7) + ((lane >> 3) & 1) * 8;
        rA128[f] = r * 128;
        rA7[f]   = r & 7;
    }
    uint32_t rB128[2], rB7[2];
    const uint32_t pB = (lane >> 3) & 1;
#pragma unroll
    for (int q = 0; q < 2; q++) {
        uint32_t r = wn * 32 + q * 16 + (lane & 7) + ((lane >> 4) & 1) * 8;
        rB128[q] = r * 128;
        rB7[q]   = r & 7;
    }

#define LOAD_FRAGS(DA, DB, SA, SB, S)                                            \
    do {                                                                         \
        _Pragma("unroll")                                                        \
        for (int _f = 0; _f < 4; _f++) {                                         \
            uint32_t _ad = (SA) + rA128[_f] + ((((2u*(S)) + pA) ^ rA7[_f]) << 4);\
            LDSM4((DA)[_f], _ad);                                                \
        }                                                                        \
        _Pragma("unroll")                                                        \
        for (int _q = 0; _q < 2; _q++) {                                         \
            uint32_t _ad = (SB) + rB128[_q] + ((((2u*(S)) + pB) ^ rB7[_q]) << 4);\
            LDSM4((DB)[_q], _ad);                                                \
        }                                                                        \
    } while (0)

    // epilogue row constants
    const int erlo = bm0 + wm * 64 + (lane >> 2);   // + f*16
    const int ecol = bn0 + wn * 32 + (lane & 3) * 2; // + n*8

    // ---- time loop ----
#pragma unroll 1
    for (int t = 1; t < S_; ++t) {
        const int par = (t - 1) & 1;
        const char*  Abase = par ? (const char*)g_h1 : (const char*)g_h0;
        __half* __restrict__ Cg = par ? g_h0 : g_h1;

        float acc[4][4][4];
#pragma unroll
        for (int f = 0; f < 4; f++)
#pragma unroll
            for (int n = 0; n < 4; n++)
#pragma unroll
                for (int k = 0; k < 4; k++) acc[f][n][k] = 0.f;

        // prologue: 3 tiles in flight
        LOAD_TILE(Abase, 0, 0);
        LOAD_TILE(Abase, 1, 1);
        LOAD_TILE(Abase, 2, 2);

        uint32_t afr[2][4][4], bfr[2][2][4];

#pragma unroll 1
        for (int it = 0; it < NKT; ++it) {
            if (it < NKT - 2)       { CP_WAIT(2); }
            else if (it == NKT - 2) { CP_WAIT(1); }
            else                    { CP_WAIT(0); }
            __syncthreads();
            if (it + 3 < NKT) LOAD_TILE(Abase, it + 3, (it + 3) & 3);

            const uint32_t sa = smA + (it & 3) * TILE_BYTES;
            const uint32_t sb = smB + (it & 3) * TILE_BYTES;

            LOAD_FRAGS(afr[0], bfr[0], sa, sb, 0);
#pragma unroll
            for (int s = 0; s < 4; s++) {
                const int cur = s & 1;
                if (s < 3) LOAD_FRAGS(afr[cur ^ 1], bfr[cur ^ 1], sa, sb, s + 1);
#pragma unroll
                for (int f = 0; f < 4; f++)
#pragma unroll
                    for (int n = 0; n < 4; n++)
                        mma16816(acc[f][n], afr[cur][f],
                                 bfr[cur][n >> 1][(n & 1) * 2],
                                 bfr[cur][n >> 1][(n & 1) * 2 + 1]);
            }
        }

        // ---- fused epilogue: + T2[x[b,t]] , tanh, fp16 store ----
#pragma unroll
        for (int f = 0; f < 4; f++) {
            int rlo = erlo + f * 16;
            int rhi = rlo + 8;
            const float* Tlo = g_T2 + x[rlo * S_ + t] * H_;
            const float* Thi = g_T2 + x[rhi * S_ + t] * H_;
#pragma unroll
            for (int n = 0; n < 4; n++) {
                int col = ecol + n * 8;
                float v0 = fast_tanh(acc[f][n][0] + Tlo[col]);
                float v1 = fast_tanh(acc[f][n][1] + Tlo[col + 1]);
                *(__half2*)(Cg + (size_t)rlo * H_ + col) = __floats2half2_rn(v0, v1);
                v0 = fast_tanh(acc[f][n][2] + Thi[col]);
                v1 = fast_tanh(acc[f][n][3] + Thi[col + 1]);
                *(__half2*)(Cg + (size_t)rhi * H_ + col) = __floats2half2_rn(v0, v1);
            }
        }

        // ---- grid barrier (skip after final step) ----
        if (t < S_ - 1) {
            __syncthreads();                 // all CTA stores done (cumulativity anchor)
            if (tid == 0) {
                asm volatile("red.release.gpu.add.u32 [%0], %1;"
                             :: "l"(&g_bar), "r"(1u) : "memory");
                unsigned tgt = 128u * (unsigned)t;
                unsigned v;
                do {
                    asm volatile("ld.acquire.gpu.u32 %0, [%1];"
                                 : "=r"(v) : "l"(&g_bar) : "memory");
                } while (v < tgt);
            }
            __syncthreads();                 // release the CTA past the barrier
        }
    }
#undef LOAD_TILE
#undef LOAD_FRAGS
}

// ---------------------------------------------------------------------------
// Output: o = hT @ W_oh^T + b_oh ; softmax over O=10 (h fp16, in g_h1)
// ---------------------------------------------------------------------------
__global__ __launch_bounds__(256)
void output_softmax_kernel(const float* __restrict__ W_oh,
                           const float* __restrict__ b_oh,
                           float* __restrict__ out) {
    const int b = blockIdx.x;
    const int tid = threadIdx.x;
    const __half* hrow = g_h1 + (size_t)b * H_;

    float acc[O_];
#pragma unroll
    for (int j = 0; j < O_; j++) acc[j] = 0.f;

    for (int k = tid; k < H_; k += 256) {
        float hv = __half2float(hrow[k]);
#pragma unroll
        for (int j = 0; j < O_; j++) acc[j] += hv * W_oh[j * H_ + k];
    }
#pragma unroll
    for (int off = 16; off > 0; off >>= 1)
#pragma unroll
        for (int j = 0; j < O_; j++)
            acc[j] += __shfl_down_sync(0xffffffffu, acc[j], off);

    __shared__ float part[8][O_];
    if ((tid & 31) == 0) {
#pragma unroll
        for (int j = 0; j < O_; j++) part[tid >> 5][j] = acc[j];
    }
    __syncthreads();

    if (tid == 0) {
        float o[O_];
#pragma unroll
        for (int j = 0; j < O_; j++) {
            float s = b_oh[j];
#pragma unroll
            for (int w = 0; w < 8; w++) s += part[w][j];
            o[j] = s;
        }
        float m = o[0];
#pragma unroll
        for (int j = 1; j < O_; j++) m = fmaxf(m, o[j]);
        float s = 0.f;
#pragma unroll
        for (int j = 0; j < O_; j++) { o[j] = expf(o[j] - m); s += o[j]; }
        float inv = 1.f / s;
#pragma unroll
        for (int j = 0; j < O_; j++) out[b * O_ + j] = o[j] * inv;
    }
}

// ---------------------------------------------------------------------------
// Launch (graph-capturable; no allocs/syncs).
// Inputs: x, embed, W_hx, b_hx, W_hh, b_hh, W_oh, b_oh
// ---------------------------------------------------------------------------
#define STEP_SMEM (1024 + 2 * NB * TILE_BYTES)

extern "C" void kernel_launch(void* const* d_in, const int* in_sizes, int n_in,
                              void* d_out, int out_size) {
    const int*   x     = (const int*)  d_in[0];
    const float* embed = (const float*)d_in[1];
    const float* W_hx  = (const float*)d_in[2];
    const float* b_hx  = (const float*)d_in[3];
    const float* W_hh  = (const float*)d_in[4];
    const float* b_hh  = (const float*)d_in[5];
    const float* W_oh  = (const float*)d_in[6];
    const float* b_oh  = (const float*)d_in[7];
    float* out = (float*)d_out;

    static int attr_set = 0;
    if (!attr_set) {
        cudaFuncSetAttribute(rnn_persist,
                             cudaFuncAttributeMaxDynamicSharedMemorySize, STEP_SMEM);
        attr_set = 1;
    }

    precompute_T_kernel<<<dim3(H_ / 256, V_), 256>>>(embed, W_hx, b_hx);
    make_T2_kernel<<<(V_ * H_) / 256, 256>>>(b_hh);
    cvt_W_kernel<<<(H_ * H_) / 256, 256>>>(W_hh);
    init_h_kernel<<<(B_ * H_) / 256, 256>>>(x);

    rnn_persist<<<dim3(H_ / BN, B_ / BM), 256, STEP_SMEM>>>(x);   // (16,8)=128 CTAs

    output_softmax_kernel<<<B_, 256>>>(W_oh, b_oh, out);
}